// round 9
// baseline (speedup 1.0000x reference)
#include <cuda_runtime.h>
#include <math.h>

// Problem constants (fixed shapes for this dataset problem)
#define NMAXN 100000
#define EMAXE 1600000

// ---------------- scratch (static __device__ — no allocations allowed) ----
__device__ float g_deg[NMAXN];                    // degree, then dinv (in place)
__device__ int2  g_edge[EMAXE];                   // {src, dst} as int32
__device__ float g_y   [(size_t)NMAXN * 64];      // (x@W1) * dinv[row]
__device__ float g_acc1[(size_t)NMAXN * 64];      // layer-1 neighbor sums
__device__ float g_y2  [(size_t)NMAXN * 16];      // (relu(out1)@W2) * dinv[row]
__device__ float g_acc2[(size_t)NMAXN * 16];      // layer-2 neighbor sums
__device__ int   g_is64;                          // edge-index dtype flag

// vector atomic add (sm_90+): one 128-bit reduction op
__device__ __forceinline__ void red_add_v4(float4* addr, float4 v) {
    asm volatile("red.global.add.v4.f32 [%0], {%1,%2,%3,%4};"
                 :: "l"(addr), "f"(v.x), "f"(v.y), "f"(v.z), "f"(v.w)
                 : "memory");
}

// ---------------- K-detect: int32 vs int64 edge buffer --------------------
// If the buffer holds int64 indices (< 2^31), every odd 32-bit word is the
// zero high-word. 256 random src indices being all zero under int32 layout
// has probability ~(1e-5)^256 — negligible.
__global__ void k_detect(const int* __restrict__ ei32) {
    if (threadIdx.x == 0 && blockIdx.x == 0) {
        int any = 0;
        #pragma unroll 8
        for (int i = 0; i < 256; i++) any |= ei32[2 * i + 1];
        g_is64 = (any == 0) ? 1 : 0;
    }
}

// ---------------- K0: init accumulators + degree (self-loop weight = 1) ---
__global__ void __launch_bounds__(256) k_init(int n) {
    int i = blockIdx.x * blockDim.x + threadIdx.x;   // float4 index space
    float4 z = make_float4(0.f, 0.f, 0.f, 0.f);
    if (i < n * 16) ((float4*)g_acc1)[i] = z;
    if (i < n * 4)  ((float4*)g_acc2)[i] = z;
    if (i < n)      g_deg[i] = 1.0f;
}

// ---------------- K1: edges -> int2, count in-degrees ---------------------
__global__ void __launch_bounds__(256) k_edges(const void* __restrict__ eiv, int e) {
    int t = blockIdx.x * blockDim.x + threadIdx.x;
    if (t >= e) return;
    int s, d;
    if (g_is64) {
        const long long* ei = (const long long*)eiv;
        s = (int)ei[t];
        d = (int)ei[t + e];
    } else {
        const int* ei = (const int*)eiv;
        s = ei[t];
        d = ei[t + e];
    }
    g_edge[t] = make_int2(s, d);
    atomicAdd(&g_deg[d], 1.0f);
}

// ---------------- K2: deg -> rsqrt(deg) ----------------------------------
__global__ void __launch_bounds__(256) k_rsqrt(int n) {
    int i = blockIdx.x * blockDim.x + threadIdx.x;
    if (i < n) g_deg[i] = rsqrtf(g_deg[i]);
}

// ---------------- K3: y = (x @ W1) * dinv[row] ----------------------------
// 64 rows per block, 256 threads: each thread = (row, 16-col group)
__global__ void __launch_bounds__(256) k_gemm1(const float* __restrict__ x,
                                               const float* __restrict__ W1, int n) {
    __shared__ float xs[64 * 68];   // padded stride 68 (bank-conflict free, 16B aligned)
    __shared__ float ws[64 * 64];
    int tid = threadIdx.x;
    int r0 = blockIdx.x * 64;
    int rows = min(64, n - r0);

    const float4* W4 = (const float4*)W1;
    float4* ws4 = (float4*)ws;
    #pragma unroll 4
    for (int i = tid; i < 1024; i += 256) ws4[i] = W4[i];

    const float4* x4 = (const float4*)(x + (size_t)r0 * 64);
    for (int i = tid; i < rows * 16; i += 256) {
        int r = i >> 4, q = i & 15;
        ((float4*)(xs + r * 68))[q] = x4[i];
    }
    __syncthreads();

    int r = tid >> 2;
    int g = (tid & 3) * 16;
    int row = r0 + r;
    if (row < n) {
        float4 a0 = make_float4(0,0,0,0), a1 = a0, a2 = a0, a3 = a0;
        #pragma unroll
        for (int k = 0; k < 64; k++) {
            float xv = xs[r * 68 + k];
            const float4* wr = (const float4*)(ws + k * 64 + g);
            float4 w0 = wr[0], w1 = wr[1], w2 = wr[2], w3 = wr[3];
            a0.x += xv * w0.x; a0.y += xv * w0.y; a0.z += xv * w0.z; a0.w += xv * w0.w;
            a1.x += xv * w1.x; a1.y += xv * w1.y; a1.z += xv * w1.z; a1.w += xv * w1.w;
            a2.x += xv * w2.x; a2.y += xv * w2.y; a2.z += xv * w2.z; a2.w += xv * w2.w;
            a3.x += xv * w3.x; a3.y += xv * w3.y; a3.z += xv * w3.z; a3.w += xv * w3.w;
        }
        float di = g_deg[row];
        float4* yo = (float4*)(g_y + (size_t)row * 64 + g);
        a0.x *= di; a0.y *= di; a0.z *= di; a0.w *= di;
        a1.x *= di; a1.y *= di; a1.z *= di; a1.w *= di;
        a2.x *= di; a2.y *= di; a2.z *= di; a2.w *= di;
        a3.x *= di; a3.y *= di; a3.z *= di; a3.w *= di;
        yo[0] = a0; yo[1] = a1; yo[2] = a2; yo[3] = a3;
    }
}

// ---------------- K4: layer-1 scatter: acc1[dst] += y[src] (64 floats) ----
// 16 lanes per edge, each lane one float4. Leader lane loads the edge pair.
__global__ void __launch_bounds__(256) k_scatter64(int e) {
    int t = blockIdx.x * blockDim.x + threadIdx.x;
    int eidx = t >> 4;
    bool valid = eidx < e;
    int ec = valid ? eidx : (e - 1);
    int lane = threadIdx.x & 31;
    int2 p = make_int2(0, 0);
    if ((lane & 15) == 0) p = g_edge[ec];
    int leader = lane & 16;
    p.x = __shfl_sync(0xffffffffu, p.x, leader);
    p.y = __shfl_sync(0xffffffffu, p.y, leader);
    int c = t & 15;
    float4 v = ((const float4*)g_y)[(size_t)p.x * 16 + c];
    if (valid) red_add_v4(((float4*)g_acc1) + (size_t)p.y * 16 + c, v);
}

// ---------------- K5: z = relu(dinv*(acc1+y)+b1); y2 = (z@W2)*dinv --------
// 16 rows per block, 16 threads per row
__global__ void __launch_bounds__(256) k_layer2(const float* __restrict__ b1,
                                                const float* __restrict__ W2, int n) {
    __shared__ float w2s[64 * 16];
    __shared__ float b1s[64];
    __shared__ float zs[16 * 65];
    int tid = threadIdx.x;
    #pragma unroll 4
    for (int i = tid; i < 1024; i += 256) w2s[i] = W2[i];
    if (tid < 64) b1s[tid] = b1[tid];
    __syncthreads();   // b1s/w2s visible before any use

    int r = tid >> 4;
    int tc = tid & 15;
    int row = blockIdx.x * 16 + r;
    bool ok = row < n;
    float di = ok ? g_deg[row] : 0.f;
    if (ok) {
        #pragma unroll
        for (int j = 0; j < 4; j++) {
            int c = tc + j * 16;
            size_t o = (size_t)row * 64 + c;
            float v = di * (g_acc1[o] + g_y[o]) + b1s[c];
            zs[r * 65 + c] = fmaxf(v, 0.f);
        }
    }
    __syncthreads();
    if (ok) {
        float acc = 0.f;
        #pragma unroll
        for (int k = 0; k < 64; k++) acc += zs[r * 65 + k] * w2s[k * 16 + tc];
        g_y2[(size_t)row * 16 + tc] = di * acc;
    }
}

// ---------------- K6: layer-2 scatter: acc2[dst] += y2[src] (16 floats) ---
// 4 lanes per edge, each lane one float4
__global__ void __launch_bounds__(256) k_scatter16(int e) {
    int t = blockIdx.x * blockDim.x + threadIdx.x;
    int eidx = t >> 2;
    bool valid = eidx < e;
    int ec = valid ? eidx : (e - 1);
    int lane = threadIdx.x & 31;
    int2 p = make_int2(0, 0);
    if ((lane & 3) == 0) p = g_edge[ec];
    int leader = lane & 28;
    p.x = __shfl_sync(0xffffffffu, p.x, leader);
    p.y = __shfl_sync(0xffffffffu, p.y, leader);
    int c = t & 3;
    float4 v = ((const float4*)g_y2)[(size_t)p.x * 4 + c];
    if (valid) red_add_v4(((float4*)g_acc2) + (size_t)p.y * 4 + c, v);
}

// ---------------- K7: out = log_softmax(dinv*(acc2+y2)+b2) ----------------
// 16 rows per block, 16 threads per row; warp reductions at width 16
__global__ void __launch_bounds__(256) k_out(const float* __restrict__ b2,
                                             float* __restrict__ out, int n) {
    int tid = threadIdx.x;
    int r = tid >> 4;
    int j = tid & 15;
    int row = blockIdx.x * 16 + r;
    float v = -1e30f;
    if (row < n) {
        float di = g_deg[row];
        size_t o = (size_t)row * 16 + j;
        v = di * (g_acc2[o] + g_y2[o]) + __ldg(&b2[j]);
    }
    float mx = v;
    #pragma unroll
    for (int m = 8; m >= 1; m >>= 1)
        mx = fmaxf(mx, __shfl_xor_sync(0xffffffffu, mx, m, 16));
    float ex = __expf(v - mx);
    float s = ex;
    #pragma unroll
    for (int m = 8; m >= 1; m >>= 1)
        s += __shfl_xor_sync(0xffffffffu, s, m, 16);
    if (row < n) out[(size_t)row * 16 + j] = (v - mx) - logf(s);
}

// ---------------- launch ---------------------------------------------------
extern "C" void kernel_launch(void* const* d_in, const int* in_sizes, int n_in,
                              void* d_out, int out_size) {
    const float* x  = (const float*)d_in[0];
    const void*  ei = d_in[1];                    // int32 or int64 — probed on device
    const float* W1 = (const float*)d_in[2];
    const float* b1 = (const float*)d_in[3];
    const float* W2 = (const float*)d_in[4];
    const float* b2 = (const float*)d_in[5];
    float* out = (float*)d_out;

    int n = in_sizes[0] / 64;       // 100000
    int e = in_sizes[1] / 2;        // 1600000 (element count same for i32/i64)

    k_detect<<<1, 32>>>((const int*)ei);
    k_init<<<(n * 16 + 255) / 256, 256>>>(n);
    k_edges<<<(e + 255) / 256, 256>>>(ei, e);
    k_rsqrt<<<(n + 255) / 256, 256>>>(n);
    k_gemm1<<<(n + 63) / 64, 256>>>(x, W1, n);
    {
        long long tt = (long long)e * 16;
        k_scatter64<<<(unsigned)((tt + 255) / 256), 256>>>(e);
    }
    k_layer2<<<(n + 15) / 16, 256>>>(b1, W2, n);
    {
        long long tt = (long long)e * 4;
        k_scatter16<<<(unsigned)((tt + 255) / 256), 256>>>(e);
    }
    k_out<<<(n + 15) / 16, 256>>>(b2, out, n);
}